// round 2
// baseline (speedup 1.0000x reference)
#include <cuda_runtime.h>

#define NN 524288
#define DD 64
#define HH 128
#define EE 8
#define AA 18
#define BN_EPS 1e-5f

typedef unsigned long long u64;

__device__ __forceinline__ u64 pk2(float lo, float hi) {
    u64 r; asm("mov.b64 %0,{%1,%2};" : "=l"(r) : "f"(lo), "f"(hi)); return r;
}
__device__ __forceinline__ void upk2(u64 v, float& lo, float& hi) {
    asm("mov.b64 {%0,%1},%2;" : "=f"(lo), "=f"(hi) : "l"(v));
}
__device__ __forceinline__ void ffma2(u64& d, u64 a, u64 b) {
    asm("fma.rn.f32x2 %0,%1,%2,%0;" : "+l"(d) : "l"(a), "l"(b));
}
__device__ __forceinline__ u64 add2(u64 a, u64 b) {
    u64 r; asm("add.rn.f32x2 %0,%1,%2;" : "=l"(r) : "l"(a), "l"(b)); return r;
}

// smem layout (floats):
//   w1s   [0,      8192)   W1 row-major [H][D]
//   w2t   [8192,   9216)   W2 transposed [H][E]
//   sbs   [9216,   9472)   interleaved (scale, bias) per j: [H][2]
//   b2s   [9472,   9488)   b2 (8 used, padded)
//   wes   [9488, ...)      We padded: stride 1156 floats per expert
#define WE_STRIDE 1156
#define SMEM_FLOATS (9488 + EE * WE_STRIDE)

__global__ __launch_bounds__(256, 2) void moe_fused(
    const float* __restrict__ X,  const float* __restrict__ W1, const float* __restrict__ b1,
    const float* __restrict__ gamma, const float* __restrict__ beta,
    const float* __restrict__ rmean, const float* __restrict__ rvar,
    const float* __restrict__ W2, const float* __restrict__ b2, const float* __restrict__ We,
    float* __restrict__ out, float* __restrict__ ret)
{
    extern __shared__ float sm[];
    float* w1s = sm;
    float* w2t = sm + 8192;
    float* sbs = sm + 9216;
    float* b2s = sm + 9472;
    float* wes = sm + 9488;

    const int tid = threadIdx.x;

    // ---- stage weights into smem ----
    {   // W1: 8192 floats = 2048 float4, coalesced
        const float4* src = (const float4*)W1;
        float4* dst = (float4*)w1s;
        #pragma unroll
        for (int i = 0; i < 8; i++) dst[tid + 256 * i] = src[tid + 256 * i];
    }
    {   // We: 8 experts x 1152 floats (288 float4), dst stride 289 float4
        const float4* src = (const float4*)We;
        float4* dst = (float4*)wes;
        for (int i = tid; i < 8 * 288; i += 256) {
            int e = i / 288, r = i % 288;
            dst[e * (WE_STRIDE / 4) + r] = src[i];
        }
    }
    // W2 transpose: w2t[j*8+e] = W2[e*H+j]
    for (int i = tid; i < HH * EE; i += 256) {
        int j = i >> 3, e = i & 7;
        w2t[i] = W2[e * HH + j];
    }
    if (tid < HH) {
        float s = gamma[tid] * rsqrtf(rvar[tid] + BN_EPS);
        sbs[2 * tid]     = s;
        sbs[2 * tid + 1] = s * (b1[tid] - rmean[tid]) + beta[tid];
    }
    if (tid < EE) b2s[tid] = b2[tid];
    __syncthreads();

    const int row = blockIdx.x * 256 + tid;

    // ---- load x row into packed f32x2 registers (64 floats = 32 u64) ----
    u64 xp[32];
    {
        const float4* px = (const float4*)(X + (size_t)row * DD);
        #pragma unroll
        for (int i = 0; i < 16; i++) {
            float4 t = px[i];
            xp[2 * i]     = pk2(t.x, t.y);
            xp[2 * i + 1] = pk2(t.z, t.w);
        }
    }

    const u64 Z = pk2(0.f, 0.f);

    // logits accumulators, init with b2
    u64 lg[4];
    #pragma unroll
    for (int k = 0; k < 4; k++) lg[k] = pk2(b2s[2 * k], b2s[2 * k + 1]);

    // ---- gating: h_j = relu(scale_j * (W1[j].x) + bias_j); logits += W2[:,j]*h_j ----
    #pragma unroll 2
    for (int j = 0; j < HH; j++) {
        const ulonglong2* pw = (const ulonglong2*)(w1s + j * DD);  // 16 x ulonglong2 per row
        u64 a0 = Z, a1 = Z, a2 = Z, a3 = Z;
        #pragma unroll
        for (int i = 0; i < 8; i++) {
            ulonglong2 w = pw[2 * i];      // floats [8i, 8i+4)
            ulonglong2 v = pw[2 * i + 1];  // floats [8i+4, 8i+8)
            ffma2(a0, w.x, xp[4 * i + 0]);
            ffma2(a1, w.y, xp[4 * i + 1]);
            ffma2(a2, v.x, xp[4 * i + 2]);
            ffma2(a3, v.y, xp[4 * i + 3]);
        }
        u64 s01 = add2(a0, a1), s23 = add2(a2, a3);
        u64 s = add2(s01, s23);
        float lo, hi; upk2(s, lo, hi);
        float dot = lo + hi;

        float2 sb = ((const float2*)sbs)[j];
        float y = fmaxf(fmaf(sb.x, dot, sb.y), 0.f);
        u64 yb = pk2(y, y);

        const ulonglong2* pw2 = (const ulonglong2*)(w2t + j * EE);
        ulonglong2 q0 = pw2[0], q1 = pw2[1];
        ffma2(lg[0], q0.x, yb);
        ffma2(lg[1], q0.y, yb);
        ffma2(lg[2], q1.x, yb);
        ffma2(lg[3], q1.y, yb);
    }

    // ---- argmax over 8 logits (first-max tie-break, matches jnp.argmax) ----
    float lf[8];
    upk2(lg[0], lf[0], lf[1]);
    upk2(lg[1], lf[2], lf[3]);
    upk2(lg[2], lf[4], lf[5]);
    upk2(lg[3], lf[6], lf[7]);
    int best = 0; float bv = lf[0];
    #pragma unroll
    for (int e = 1; e < 8; e++) {
        if (lf[e] > bv) { bv = lf[e]; best = e; }
    }

    // ---- selected-expert GEMV: out[row] = We[best] @ x ----
    {
        const ulonglong2* pe = (const ulonglong2*)(wes + best * WE_STRIDE);
        float* orow = out + (size_t)row * AA;
        #pragma unroll
        for (int a = 0; a < AA; a++) {
            u64 a0 = Z, a1 = Z, a2 = Z, a3 = Z;
            #pragma unroll
            for (int i = 0; i < 8; i++) {
                ulonglong2 w = pe[a * 16 + 2 * i];
                ulonglong2 v = pe[a * 16 + 2 * i + 1];
                ffma2(a0, w.x, xp[4 * i + 0]);
                ffma2(a1, w.y, xp[4 * i + 1]);
                ffma2(a2, v.x, xp[4 * i + 2]);
                ffma2(a3, v.y, xp[4 * i + 3]);
            }
            u64 s = add2(add2(a0, a1), add2(a2, a3));
            float lo, hi; upk2(s, lo, hi);
            orow[a] = lo + hi;
        }
    }

    // ---- ret: one-hot ----
    {
        float rr[8];
        #pragma unroll
        for (int e = 0; e < 8; e++) rr[e] = (e == best) ? 1.0f : 0.0f;
        float4* pr = (float4*)(ret + (size_t)row * EE);
        pr[0] = make_float4(rr[0], rr[1], rr[2], rr[3]);
        pr[1] = make_float4(rr[4], rr[5], rr[6], rr[7]);
    }
}

extern "C" void kernel_launch(void* const* d_in, const int* in_sizes, int n_in,
                              void* d_out, int out_size) {
    const float* X     = (const float*)d_in[0];
    const float* W1    = (const float*)d_in[1];
    const float* b1    = (const float*)d_in[2];
    const float* gamma = (const float*)d_in[3];
    const float* beta  = (const float*)d_in[4];
    const float* rmean = (const float*)d_in[5];
    const float* rvar  = (const float*)d_in[6];
    const float* W2    = (const float*)d_in[7];
    const float* b2    = (const float*)d_in[8];
    const float* We    = (const float*)d_in[9];

    float* out = (float*)d_out;                    // [N, A] first
    float* ret = out + (size_t)NN * AA;            // then [N, E]

    size_t smem = SMEM_FLOATS * sizeof(float);
    static bool attr_set = false;
    if (!attr_set) {
        cudaFuncSetAttribute(moe_fused, cudaFuncAttributeMaxDynamicSharedMemorySize, (int)smem);
        attr_set = true;
    }
    moe_fused<<<NN / 256, 256, smem>>>(X, W1, b1, gamma, beta, rmean, rvar, W2, b2, We, out, ret);
}